// round 9
// baseline (speedup 1.0000x reference)
#include <cuda_runtime.h>
#include <cuda_fp16.h>
#include <math.h>

#define BB   32
#define CC   2048
#define HWN  576
#define HW4  144       // HWN / 4
#define PP   4
#define CHID 128
#define CP   8192
#define BCHUNK 16
#define NHWC 9         // hw chunks of 64

// einsum staging: 8 stages x 256 channels, 3-slot ring
#define NST        8
#define STCH       256
#define CH_STRIDE  80                      // 64B data + 16B pad
#define SLOT_BYTES (STCH * CH_STRIDE)      // 20480
#define RING_BYTES (3 * SLOT_BYTES)        // 61440
#define SMEM_WCOMB RING_BYTES
#define SMEM_SBETA (SMEM_WCOMB + CC * 16)  // 94208
#define SMEM_TOT   (SMEM_SBETA + 32)

// ---- scratch (no allocations allowed) ----
__device__ unsigned int g_xq[BB * CC * HW4];       // 37.7 MB e4m3 copy of x
__device__ float g_pooled[BB * CC];
__device__ float g_hidden[BB * CHID];
__device__ float g_dw[BB * CP];
__device__ float g_beta_part[BCHUNK * BB * PP];

__device__ __forceinline__ unsigned int smem_u32(const void* p) {
    unsigned int a;
    asm("{ .reg .u64 t; cvta.to.shared.u64 t, %1; cvt.u32.u64 %0, t; }"
        : "=r"(a) : "l"(p));
    return a;
}
__device__ __forceinline__ void cp_async16(unsigned int dst, const void* src) {
    asm volatile("cp.async.cg.shared.global [%0], [%1], 16;" :: "r"(dst), "l"(src));
}
__device__ __forceinline__ unsigned long long dup2(float f) {
    unsigned long long r;
    asm("mov.b64 %0, {%1, %1};" : "=l"(r) : "f"(f));
    return r;
}
__device__ __forceinline__ unsigned long long ffma2(unsigned long long a,
                                                    unsigned long long b,
                                                    unsigned long long c) {
    unsigned long long r;
    asm("fma.rn.f32x2 %0, %1, %2, %3;" : "=l"(r) : "l"(a), "l"(b), "l"(c));
    return r;
}
__device__ __forceinline__ float2 unpk2(unsigned long long v) {
    float2 f;
    asm("mov.b64 {%0, %1}, %2;" : "=f"(f.x), "=f"(f.y) : "l"(v));
    return f;
}

// ============================================================
// 1) pooled[b,c] = mean over HW; also write e4m3 copy of x.
// ============================================================
__global__ void k_pool(const float* __restrict__ x) {
    int warp = (blockIdx.x * blockDim.x + threadIdx.x) >> 5;
    int lane = threadIdx.x & 31;
    const float4* xr = reinterpret_cast<const float4*>(x) + (size_t)warp * HW4;
    unsigned int* xw = g_xq + (size_t)warp * HW4;
    float s = 0.f;
    #pragma unroll
    for (int k = lane; k < HW4; k += 32) {
        float4 v = __ldcs(&xr[k]);
        s += (v.x + v.y) + (v.z + v.w);
        unsigned int u;
        asm("{\n\t"
            ".reg .b16 lo, hi;\n\t"
            "cvt.rn.satfinite.e4m3x2.f32 lo, %2, %1;\n\t"
            "cvt.rn.satfinite.e4m3x2.f32 hi, %4, %3;\n\t"
            "mov.b32 %0, {lo, hi};\n\t"
            "}" : "=r"(u) : "f"(v.x), "f"(v.y), "f"(v.z), "f"(v.w));
        xw[k] = u;
    }
    #pragma unroll
    for (int o = 16; o; o >>= 1) s += __shfl_xor_sync(0xffffffffu, s, o);
    if (lane == 0) g_pooled[warp] = s * (1.0f / 576.0f);
}

// ============================================================
// 2) hidden[b,j] = silu(dot(pooled[b,:], fc1_w[j,:]) + fc1_b[j])
// ============================================================
__global__ void k_fc1(const float* __restrict__ fc1_w,
                      const float* __restrict__ fc1_b) {
    int warp = (blockIdx.x * blockDim.x + threadIdx.x) >> 5;
    int lane = threadIdx.x & 31;
    int b = warp >> 7;
    int j = warp & 127;
    const float4* pr = reinterpret_cast<const float4*>(g_pooled) + (size_t)b * (CC / 4);
    const float4* wr = reinterpret_cast<const float4*>(fc1_w)    + (size_t)j * (CC / 4);
    float s = 0.f;
    #pragma unroll 4
    for (int k = lane; k < CC / 4; k += 32) {
        float4 a = pr[k];
        float4 w = __ldg(&wr[k]);
        s += a.x * w.x + a.y * w.y + a.z * w.z + a.w * w.w;
    }
    #pragma unroll
    for (int o = 16; o; o >>= 1) s += __shfl_xor_sync(0xffffffffu, s, o);
    if (lane == 0) {
        float z = s + fc1_b[j];
        g_hidden[b * CHID + j] = z / (1.0f + expf(-z));
    }
}

// ============================================================
// 3) dw + fused beta partials. 256 blocks x 128 threads:
//    rc = 128-row chunk (0..63), bg = 8-batch group (0..3).
// ============================================================
__global__ void k_fc2(const float* __restrict__ fc2_w,
                      const float* __restrict__ fc2_b,
                      const float* __restrict__ conv_b) {
    __shared__ float4 hs[8 * 32];
    __shared__ float  red[8][128];
    int rc = blockIdx.x & 63;
    int bg = blockIdx.x >> 6;
    int t  = threadIdx.x;              // 0..127

    hs[t]       = reinterpret_cast<const float4*>(g_hidden)[bg * 256 + t];
    hs[t + 128] = reinterpret_cast<const float4*>(g_hidden)[bg * 256 + 128 + t];
    __syncthreads();

    int row = rc * 128 + t;
    int p   = row >> 11;
    int c   = row & 2047;
    int chi = c >> 7;                  // 0..15
    const float4* wr = reinterpret_cast<const float4*>(fc2_w) + (size_t)row * 32;
    float acc[8];
    #pragma unroll
    for (int bb = 0; bb < 8; bb++) acc[bb] = 0.f;

    #pragma unroll 4
    for (int j4 = 0; j4 < 32; j4++) {
        float4 w = __ldg(&wr[j4]);
        #pragma unroll
        for (int bb = 0; bb < 8; bb++) {
            float4 h = hs[bb * 32 + j4];
            acc[bb] += w.x * h.x + w.y * h.y + w.z * h.z + w.w * h.w;
        }
    }
    float bias = fc2_b[row];
    float cb   = __ldg(&conv_b[c]);
    #pragma unroll
    for (int bb = 0; bb < 8; bb++) {
        float d = acc[bb] + bias;
        g_dw[(size_t)(bg * 8 + bb) * CP + row] = d;
        red[bb][t] = cb * d;
    }
    __syncthreads();

    int wid  = t >> 5;
    int lane = t & 31;
    #pragma unroll
    for (int k = 0; k < 2; k++) {
        int bb = wid * 2 + k;
        float s = red[bb][lane] + red[bb][lane + 32] +
                  red[bb][lane + 64] + red[bb][lane + 96];
        #pragma unroll
        for (int o = 16; o; o >>= 1) s += __shfl_xor_sync(0xffffffffu, s, o);
        if (lane == 0)
            g_beta_part[((size_t)chi * BB + bg * 8 + bb) * PP + p] = s;
    }
}

// ============================================================
// 4) Fused einsum + softmax. 8 stages x 256ch, 3-slot cp.async ring,
//    f32x2 FFMA2 accumulation (p-pairs packed in u64).
//    Block = (b, 64-hw chunk). 512 thr = 16 warps.
//    Warp w: stage channels [w*16, w*16+16), 2/iter (half=lane>>4).
// ============================================================
__global__ void __launch_bounds__(512, 2) k_einsum(const float* __restrict__ conv_w,
                                                   float* __restrict__ out) {
    extern __shared__ char smem[];
    float4* wcomb = reinterpret_cast<float4*>(smem + SMEM_WCOMB);   // [CC]
    float*  sbeta = reinterpret_cast<float*>(smem + SMEM_SBETA);
    // red aliases ring slot 0 (dead after the last stage is consumed)
    float4 (*red)[16][4] = reinterpret_cast<float4 (*)[16][4]>(smem);
    unsigned int xs_base = smem_u32(smem);

    int blk = blockIdx.x;
    int b   = blk / NHWC;
    int hc  = blk % NHWC;
    int t   = threadIdx.x;
    int w   = t >> 5;
    int lane = t & 31;
    int half = lane >> 4;
    int qi   = lane & 15;

    // copy geometry: stage = 1024 x 16B chunks, 512 threads x 2 chunks
    int ch0 = t >> 2,        ck0 = t & 3;
    int ch1 = (t + 512) >> 2, ck1 = t & 3;   // t+512: ck = (t+512)&3 == t&3
    unsigned int d0 = xs_base + ch0 * CH_STRIDE + ck0 * 16;
    unsigned int d1 = xs_base + ch1 * CH_STRIDE + ck1 * 16;
    const unsigned int* s0 = g_xq + ((size_t)b * CC + ch0) * HW4 + hc * 16 + ck0 * 4;
    const unsigned int* s1 = g_xq + ((size_t)b * CC + ch1) * HW4 + hc * 16 + ck1 * 4;

    // prologue: stages 0,1 -> slots 0,1
    #pragma unroll
    for (int s = 0; s < 2; s++) {
        cp_async16(d0 + s * SLOT_BYTES, s0 + (size_t)(s * STCH) * HW4);
        cp_async16(d1 + s * SLOT_BYTES, s1 + (size_t)(s * STCH) * HW4);
        asm volatile("cp.async.commit_group;");
    }

    if (t < PP) {
        float bsum = 0.f;
        #pragma unroll
        for (int chi = 0; chi < BCHUNK; chi++)
            bsum += g_beta_part[((size_t)chi * BB + b) * PP + t];
        sbeta[t] = bsum;
    }
    const float* dwb = g_dw + (size_t)b * CP;
    for (int idx = t; idx < CC * PP; idx += 512) {
        int c = idx >> 2;
        int p = idx & 3;
        reinterpret_cast<float*>(wcomb)[idx] = __ldg(&conv_w[c]) * dwb[p * CC + c];
    }

    unsigned long long acc2[4][2];
    #pragma unroll
    for (int h = 0; h < 4; h++) { acc2[h][0] = 0ull; acc2[h][1] = 0ull; }

    #pragma unroll
    for (int s = 0; s < NST; s++) {
        if (s < NST - 1) asm volatile("cp.async.wait_group 1;");
        else             asm volatile("cp.async.wait_group 0;");
        __syncthreads();

        if (s < NST - 2) {
            int ss = s + 2;
            int slot = ss % 3;
            cp_async16(d0 + slot * SLOT_BYTES, s0 + (size_t)(ss * STCH) * HW4);
            cp_async16(d1 + slot * SLOT_BYTES, s1 + (size_t)(ss * STCH) * HW4);
            asm volatile("cp.async.commit_group;");
        }

        const char* stg = smem + (s % 3) * SLOT_BYTES;
        #pragma unroll
        for (int i = 0; i < 8; i++) {
            int ch = (w << 4) + (i << 1) + half;
            unsigned int v = *reinterpret_cast<const unsigned int*>(
                                 stg + ch * CH_STRIDE + qi * 4);
            unsigned int h2lo, h2hi;
            asm("{\n\t"
                ".reg .b16 a, bz;\n\t"
                "mov.b32 {a, bz}, %2;\n\t"
                "cvt.rn.f16x2.e4m3x2 %0, a;\n\t"
                "cvt.rn.f16x2.e4m3x2 %1, bz;\n\t"
                "}" : "=r"(h2lo), "=r"(h2hi) : "r"(v));
            float2 f01 = __half22float2(*reinterpret_cast<__half2*>(&h2lo));
            float2 f23 = __half22float2(*reinterpret_cast<__half2*>(&h2hi));
            ulonglong2 wc2 = *reinterpret_cast<const ulonglong2*>(&wcomb[(s << 8) + ch]);
            unsigned long long q0 = dup2(f01.x), q1 = dup2(f01.y);
            unsigned long long q2 = dup2(f23.x), q3 = dup2(f23.y);
            acc2[0][0] = ffma2(q0, wc2.x, acc2[0][0]);
            acc2[0][1] = ffma2(q0, wc2.y, acc2[0][1]);
            acc2[1][0] = ffma2(q1, wc2.x, acc2[1][0]);
            acc2[1][1] = ffma2(q1, wc2.y, acc2[1][1]);
            acc2[2][0] = ffma2(q2, wc2.x, acc2[2][0]);
            acc2[2][1] = ffma2(q2, wc2.y, acc2[2][1]);
            acc2[3][0] = ffma2(q3, wc2.x, acc2[3][0]);
            acc2[3][1] = ffma2(q3, wc2.y, acc2[3][1]);
        }
    }

    // unpack + fold channel halves (lane i += lane i+16)
    float acc[4][4];
    #pragma unroll
    for (int h = 0; h < 4; h++) {
        float2 a01 = unpk2(acc2[h][0]);
        float2 a23 = unpk2(acc2[h][1]);
        acc[h][0] = a01.x; acc[h][1] = a01.y; acc[h][2] = a23.x; acc[h][3] = a23.y;
    }
    #pragma unroll
    for (int h = 0; h < 4; h++)
        #pragma unroll
        for (int p = 0; p < 4; p++)
            acc[h][p] += __shfl_down_sync(0xffffffffu, acc[h][p], 16);

    if (half == 0) {
        #pragma unroll
        for (int h = 0; h < 4; h++)
            red[w][qi][h] = make_float4(acc[h][0], acc[h][1], acc[h][2], acc[h][3]);
    }
    __syncthreads();

    if (t < 64) {
        int rq = t >> 2;
        int rh = t & 3;
        float4 s = {0, 0, 0, 0};
        #pragma unroll
        for (int st = 0; st < 16; st++) {
            float4 v = red[st][rq][rh];
            s.x += v.x; s.y += v.y; s.z += v.z; s.w += v.w;
        }
        s.x += sbeta[0]; s.y += sbeta[1]; s.z += sbeta[2]; s.w += sbeta[3];
        float m = fmaxf(fmaxf(s.x, s.y), fmaxf(s.z, s.w));
        float e0 = expf(s.x - m), e1 = expf(s.y - m), e2 = expf(s.z - m), e3 = expf(s.w - m);
        float inv = 1.f / (e0 + e1 + e2 + e3);
        size_t base = ((size_t)b * PP) * HWN + hc * 64 + t;
        out[base + 0 * HWN] = e0 * inv;
        out[base + 1 * HWN] = e1 * inv;
        out[base + 2 * HWN] = e2 * inv;
        out[base + 3 * HWN] = e3 * inv;
    }
}

extern "C" void kernel_launch(void* const* d_in, const int* in_sizes, int n_in,
                              void* d_out, int out_size) {
    const float* x      = (const float*)d_in[0];
    const float* fc1_w  = (const float*)d_in[1];
    const float* fc1_b  = (const float*)d_in[2];
    const float* fc2_w  = (const float*)d_in[3];
    const float* fc2_b  = (const float*)d_in[4];
    const float* conv_w = (const float*)d_in[5];
    const float* conv_b = (const float*)d_in[6];
    float* out = (float*)d_out;

    static int smem_set = 0;
    if (!smem_set) {
        cudaFuncSetAttribute(k_einsum, cudaFuncAttributeMaxDynamicSharedMemorySize,
                             SMEM_TOT);
        smem_set = 1;
    }

    k_pool  <<<(BB * CC) / 8, 256>>>(x);
    k_fc1   <<<(BB * CHID) / 8, 256>>>(fc1_w, fc1_b);
    k_fc2   <<<256, 128>>>(fc2_w, fc2_b, conv_b);
    k_einsum<<<BB * NHWC, 512, SMEM_TOT>>>(conv_w, out);
}

// round 10
// speedup vs baseline: 1.3307x; 1.3307x over previous
#include <cuda_runtime.h>
#include <cuda_fp16.h>
#include <math.h>

#define BB   32
#define CC   2048
#define HWN  576
#define HW4  144       // HWN / 4
#define PP   4
#define CHID 128
#define CP   8192
#define BCHUNK 8
#define NHWC 9         // hw chunks of 64

// einsum: warp-private staging. Warp owns 128 channels;
// 8 warp-stages x 16 channels; 4-slot ring of 1 KB per warp.
#define WRING_B    4096                    // per-warp ring bytes
#define SMEM_WCOMB (16 * WRING_B)          // 65536
#define SMEM_TOT   (SMEM_WCOMB + CC * 16)  // 98304

// ---- scratch (no allocations allowed) ----
__device__ unsigned int g_xq[BB * CC * HW4];       // 37.7 MB e4m3 copy of x
__device__ float g_pooled[BB * CC];
__device__ float g_hidden[BB * CHID];
__device__ float g_dw[BB * CP];
__device__ float g_beta_part[BCHUNK * BB * PP];

__device__ __forceinline__ unsigned int smem_u32(const void* p) {
    unsigned int a;
    asm("{ .reg .u64 t; cvta.to.shared.u64 t, %1; cvt.u32.u64 %0, t; }"
        : "=r"(a) : "l"(p));
    return a;
}
__device__ __forceinline__ void cp_async16(unsigned int dst, const void* src) {
    asm volatile("cp.async.cg.shared.global [%0], [%1], 16;" :: "r"(dst), "l"(src));
}

// ============================================================
// 1) pooled[b,c] = mean over HW; also write e4m3 copy of x.
// ============================================================
__global__ void k_pool(const float* __restrict__ x) {
    int warp = (blockIdx.x * blockDim.x + threadIdx.x) >> 5;
    int lane = threadIdx.x & 31;
    const float4* xr = reinterpret_cast<const float4*>(x) + (size_t)warp * HW4;
    unsigned int* xw = g_xq + (size_t)warp * HW4;
    float s = 0.f;
    #pragma unroll
    for (int k = lane; k < HW4; k += 32) {
        float4 v = __ldcs(&xr[k]);
        s += (v.x + v.y) + (v.z + v.w);
        unsigned int u;
        asm("{\n\t"
            ".reg .b16 lo, hi;\n\t"
            "cvt.rn.satfinite.e4m3x2.f32 lo, %2, %1;\n\t"
            "cvt.rn.satfinite.e4m3x2.f32 hi, %4, %3;\n\t"
            "mov.b32 %0, {lo, hi};\n\t"
            "}" : "=r"(u) : "f"(v.x), "f"(v.y), "f"(v.z), "f"(v.w));
        xw[k] = u;
    }
    #pragma unroll
    for (int o = 16; o; o >>= 1) s += __shfl_xor_sync(0xffffffffu, s, o);
    if (lane == 0) g_pooled[warp] = s * (1.0f / 576.0f);
}

// ============================================================
// 2) hidden[b,j] = silu(dot(pooled[b,:], fc1_w[j,:]) + fc1_b[j])
// ============================================================
__global__ void k_fc1(const float* __restrict__ fc1_w,
                      const float* __restrict__ fc1_b) {
    int warp = (blockIdx.x * blockDim.x + threadIdx.x) >> 5;
    int lane = threadIdx.x & 31;
    int b = warp >> 7;
    int j = warp & 127;
    const float4* pr = reinterpret_cast<const float4*>(g_pooled) + (size_t)b * (CC / 4);
    const float4* wr = reinterpret_cast<const float4*>(fc1_w)    + (size_t)j * (CC / 4);
    float s = 0.f;
    #pragma unroll 4
    for (int k = lane; k < CC / 4; k += 32) {
        float4 a = pr[k];
        float4 w = __ldg(&wr[k]);
        s += a.x * w.x + a.y * w.y + a.z * w.z + a.w * w.w;
    }
    #pragma unroll
    for (int o = 16; o; o >>= 1) s += __shfl_xor_sync(0xffffffffu, s, o);
    if (lane == 0) {
        float z = s + fc1_b[j];
        g_hidden[b * CHID + j] = z / (1.0f + expf(-z));
    }
}

// ============================================================
// 3) dw + fused beta partials (r8 config: 128 blocks x 256 thr).
// ============================================================
__global__ void k_fc2(const float* __restrict__ fc2_w,
                      const float* __restrict__ fc2_b,
                      const float* __restrict__ conv_b) {
    __shared__ float4 hs[8 * 32];
    __shared__ float  red[8][256];
    int rc = blockIdx.x & 31;
    int bg = blockIdx.x >> 5;
    int t  = threadIdx.x;

    hs[t] = reinterpret_cast<const float4*>(g_hidden)[bg * 256 + t];
    __syncthreads();

    int row = rc * 256 + t;
    int p   = rc >> 3;
    int chi = rc & 7;
    int c   = chi * 256 + t;
    const float4* wr = reinterpret_cast<const float4*>(fc2_w) + (size_t)row * 32;
    float acc[8];
    #pragma unroll
    for (int bb = 0; bb < 8; bb++) acc[bb] = 0.f;

    #pragma unroll 4
    for (int j4 = 0; j4 < 32; j4++) {
        float4 w = __ldg(&wr[j4]);
        #pragma unroll
        for (int bb = 0; bb < 8; bb++) {
            float4 h = hs[bb * 32 + j4];
            acc[bb] += w.x * h.x + w.y * h.y + w.z * h.z + w.w * h.w;
        }
    }
    float bias = fc2_b[row];
    float cb   = __ldg(&conv_b[c]);
    #pragma unroll
    for (int bb = 0; bb < 8; bb++) {
        float d = acc[bb] + bias;
        g_dw[(size_t)(bg * 8 + bb) * CP + row] = d;
        red[bb][t] = cb * d;
    }
    __syncthreads();

    int wid  = t >> 5;
    int lane = t & 31;
    float s = red[wid][lane] + red[wid][lane + 32] + red[wid][lane + 64] +
              red[wid][lane + 96] + red[wid][lane + 128] + red[wid][lane + 160] +
              red[wid][lane + 192] + red[wid][lane + 224];
    #pragma unroll
    for (int o = 16; o; o >>= 1) s += __shfl_xor_sync(0xffffffffu, s, o);
    if (lane == 0)
        g_beta_part[((size_t)chi * BB + bg * 8 + wid) * PP + p] = s;
}

// ============================================================
// 4) Fused einsum + softmax with WARP-PRIVATE cp.async pipelines.
//    Block = (b, 64-hw chunk). 512 thr = 16 warps.
//    Warp w owns channels [w*128, (w+1)*128): 8 warp-stages of
//    16 ch (1 KB), private 4-slot ring, __syncwarp only.
//    Lane: half = lane>>4 (channel of pair), qi = lane&15 (4-hw quad).
// ============================================================
__global__ void __launch_bounds__(512, 2) k_einsum(const float* __restrict__ conv_w,
                                                   float* __restrict__ out) {
    extern __shared__ char smem[];
    float4* wcomb = reinterpret_cast<float4*>(smem + SMEM_WCOMB);  // [CC]
    unsigned int xs_base = smem_u32(smem);

    int blk = blockIdx.x;
    int b   = blk / NHWC;
    int hc  = blk % NHWC;
    int t   = threadIdx.x;
    int w   = t >> 5;
    int lane = t & 31;
    int half = lane >> 4;
    int qi   = lane & 15;

    unsigned int wring = xs_base + w * WRING_B;

    // copy geometry: warp-stage = 16 ch x 64 B = 64 x 16B chunks.
    // lane handles chunks lane and lane+32.
    int chA = lane >> 2, ckA = lane & 3;      // chunks 0..31 -> ch 0..7
    int chB = chA + 8;                        // chunks 32..63 -> ch 8..15
    unsigned int dA = wring + chA * 64 + ckA * 16;
    unsigned int dB = wring + chB * 64 + ckA * 16;
    const unsigned int* sA = g_xq + ((size_t)b * CC + w * 128 + chA) * HW4
                                  + hc * 16 + ckA * 4;
    const unsigned int* sB = g_xq + ((size_t)b * CC + w * 128 + chB) * HW4
                                  + hc * 16 + ckA * 4;

    // prologue: warp-stages 0,1,2 -> slots 0,1,2
    #pragma unroll
    for (int s = 0; s < 3; s++) {
        cp_async16(dA + s * 1024, sA + (size_t)(s * 16) * HW4);
        cp_async16(dB + s * 1024, sB + (size_t)(s * 16) * HW4);
        asm volatile("cp.async.commit_group;");
    }

    // wcomb fill (overlaps the prologue copies)
    const float* dwb = g_dw + (size_t)b * CP;
    for (int idx = t; idx < CC * PP; idx += 512) {
        int c = idx >> 2;
        int p = idx & 3;
        reinterpret_cast<float*>(wcomb)[idx] = __ldg(&conv_w[c]) * dwb[p * CC + c];
    }
    __syncthreads();   // wcomb visible to all warps (only block barrier pre-loop)

    float acc[4][4];
    #pragma unroll
    for (int h = 0; h < 4; h++)
        #pragma unroll
        for (int p = 0; p < 4; p++) acc[h][p] = 0.f;

    #pragma unroll
    for (int s = 0; s < 8; s++) {
        // wait for warp-stage s (pending: s..min(s+2,7))
        if (s <= 5)      asm volatile("cp.async.wait_group 2;");
        else if (s == 6) asm volatile("cp.async.wait_group 1;");
        else             asm volatile("cp.async.wait_group 0;");
        __syncwarp();

        if (s <= 4) {    // refill slot (s+3)&3 (warp-local reuse: safe)
            int ss = s + 3;
            cp_async16(dA + (ss & 3) * 1024, sA + (size_t)(ss * 16) * HW4);
            cp_async16(dB + (ss & 3) * 1024, sB + (size_t)(ss * 16) * HW4);
            asm volatile("cp.async.commit_group;");
        }

        const char* stg = smem + w * WRING_B + (s & 3) * 1024;
        #pragma unroll
        for (int i = 0; i < 8; i++) {
            int chl = (i << 1) + half;                 // 0..15
            unsigned int v = *reinterpret_cast<const unsigned int*>(
                                 stg + chl * 64 + qi * 4);
            unsigned int h2lo, h2hi;
            asm("{\n\t"
                ".reg .b16 a, bz;\n\t"
                "mov.b32 {a, bz}, %2;\n\t"
                "cvt.rn.f16x2.e4m3x2 %0, a;\n\t"
                "cvt.rn.f16x2.e4m3x2 %1, bz;\n\t"
                "}" : "=r"(h2lo), "=r"(h2hi) : "r"(v));
            float2 f01 = __half22float2(*reinterpret_cast<__half2*>(&h2lo));
            float2 f23 = __half22float2(*reinterpret_cast<__half2*>(&h2hi));
            float4 wc = wcomb[(w << 7) + (s << 4) + chl];
            acc[0][0] = fmaf(f01.x, wc.x, acc[0][0]); acc[0][1] = fmaf(f01.x, wc.y, acc[0][1]);
            acc[0][2] = fmaf(f01.x, wc.z, acc[0][2]); acc[0][3] = fmaf(f01.x, wc.w, acc[0][3]);
            acc[1][0] = fmaf(f01.y, wc.x, acc[1][0]); acc[1][1] = fmaf(f01.y, wc.y, acc[1][1]);
            acc[1][2] = fmaf(f01.y, wc.z, acc[1][2]); acc[1][3] = fmaf(f01.y, wc.w, acc[1][3]);
            acc[2][0] = fmaf(f23.x, wc.x, acc[2][0]); acc[2][1] = fmaf(f23.x, wc.y, acc[2][1]);
            acc[2][2] = fmaf(f23.x, wc.z, acc[2][2]); acc[2][3] = fmaf(f23.x, wc.w, acc[2][3]);
            acc[3][0] = fmaf(f23.y, wc.x, acc[3][0]); acc[3][1] = fmaf(f23.y, wc.y, acc[3][1]);
            acc[3][2] = fmaf(f23.y, wc.z, acc[3][2]); acc[3][3] = fmaf(f23.y, wc.w, acc[3][3]);
        }
    }

    // fold channel halves: lane i += lane i+16 (same qi)
    #pragma unroll
    for (int h = 0; h < 4; h++)
        #pragma unroll
        for (int p = 0; p < 4; p++)
            acc[h][p] += __shfl_down_sync(0xffffffffu, acc[h][p], 16);

    // stash into this warp's (now dead) ring region: [qi][h] -> float4 over p
    if (half == 0) {
        float4* red = reinterpret_cast<float4*>(smem + w * WRING_B);
        #pragma unroll
        for (int h = 0; h < 4; h++)
            red[qi * 4 + h] = make_float4(acc[h][0], acc[h][1], acc[h][2], acc[h][3]);
    }
    __syncthreads();

    // 64 threads: thread owns hw = rq*4 + rh; sum 16 warps + beta, softmax
    if (t < 64) {
        int rq = t >> 2;
        int rh = t & 3;
        float4 s = {0, 0, 0, 0};
        #pragma unroll
        for (int st = 0; st < 16; st++) {
            float4 v = reinterpret_cast<const float4*>(smem + st * WRING_B)[rq * 4 + rh];
            s.x += v.x; s.y += v.y; s.z += v.z; s.w += v.w;
        }
        #pragma unroll
        for (int chi = 0; chi < BCHUNK; chi++) {
            float4 bv = *reinterpret_cast<const float4*>(
                            &g_beta_part[((size_t)chi * BB + b) * PP]);
            s.x += bv.x; s.y += bv.y; s.z += bv.z; s.w += bv.w;
        }
        float m = fmaxf(fmaxf(s.x, s.y), fmaxf(s.z, s.w));
        float e0 = expf(s.x - m), e1 = expf(s.y - m), e2 = expf(s.z - m), e3 = expf(s.w - m);
        float inv = 1.f / (e0 + e1 + e2 + e3);
        size_t base = ((size_t)b * PP) * HWN + hc * 64 + t;
        out[base + 0 * HWN] = e0 * inv;
        out[base + 1 * HWN] = e1 * inv;
        out[base + 2 * HWN] = e2 * inv;
        out[base + 3 * HWN] = e3 * inv;
    }
}

extern "C" void kernel_launch(void* const* d_in, const int* in_sizes, int n_in,
                              void* d_out, int out_size) {
    const float* x      = (const float*)d_in[0];
    const float* fc1_w  = (const float*)d_in[1];
    const float* fc1_b  = (const float*)d_in[2];
    const float* fc2_w  = (const float*)d_in[3];
    const float* fc2_b  = (const float*)d_in[4];
    const float* conv_w = (const float*)d_in[5];
    const float* conv_b = (const float*)d_in[6];
    float* out = (float*)d_out;

    static int smem_set = 0;
    if (!smem_set) {
        cudaFuncSetAttribute(k_einsum, cudaFuncAttributeMaxDynamicSharedMemorySize,
                             SMEM_TOT);
        smem_set = 1;
    }

    k_pool  <<<(BB * CC) / 8, 256>>>(x);
    k_fc1   <<<(BB * CHID) / 8, 256>>>(fc1_w, fc1_b);
    k_fc2   <<<128, 256>>>(fc2_w, fc2_b, conv_b);
    k_einsum<<<BB * NHWC, 512, SMEM_TOT>>>(conv_w, out);
}

// round 11
// speedup vs baseline: 1.3763x; 1.0342x over previous
#include <cuda_runtime.h>
#include <cuda_fp16.h>
#include <math.h>

#define BB   32
#define CC   2048
#define HWN  576
#define HW4  144       // HWN / 4
#define PP   4
#define CHID 128
#define CP   8192
#define BCHUNK 8
#define NHWC 9         // hw chunks of 64

// einsum: warp-private staging. Warp owns 128 channels;
// 8 warp-stages x 16 channels; 4-slot ring of 1 KB per warp.
#define WRING_B    4096                    // per-warp ring bytes
#define SMEM_WCOMB (16 * WRING_B)          // 65536
#define SMEM_TOT   (SMEM_WCOMB + CC * 16)  // 98304 (wcomb: 4 h2 per channel)

// ---- scratch (no allocations allowed) ----
__device__ unsigned int g_xq[BB * CC * HW4];       // 37.7 MB e4m3 copy of x
__device__ float g_pooled[BB * CC];
__device__ float g_hidden[BB * CHID];
__device__ float g_dw[BB * CP];
__device__ float g_beta_part[BCHUNK * BB * PP];

__device__ __forceinline__ unsigned int smem_u32(const void* p) {
    unsigned int a;
    asm("{ .reg .u64 t; cvta.to.shared.u64 t, %1; cvt.u32.u64 %0, t; }"
        : "=r"(a) : "l"(p));
    return a;
}
__device__ __forceinline__ void cp_async16(unsigned int dst, const void* src) {
    asm volatile("cp.async.cg.shared.global [%0], [%1], 16;" :: "r"(dst), "l"(src));
}

// ============================================================
// 1) pooled[b,c] = mean over HW; also write e4m3 copy of x.
// ============================================================
__global__ void k_pool(const float* __restrict__ x) {
    int warp = (blockIdx.x * blockDim.x + threadIdx.x) >> 5;
    int lane = threadIdx.x & 31;
    const float4* xr = reinterpret_cast<const float4*>(x) + (size_t)warp * HW4;
    unsigned int* xw = g_xq + (size_t)warp * HW4;
    float s = 0.f;
    #pragma unroll
    for (int k = lane; k < HW4; k += 32) {
        float4 v = __ldcs(&xr[k]);
        s += (v.x + v.y) + (v.z + v.w);
        unsigned int u;
        asm("{\n\t"
            ".reg .b16 lo, hi;\n\t"
            "cvt.rn.satfinite.e4m3x2.f32 lo, %2, %1;\n\t"
            "cvt.rn.satfinite.e4m3x2.f32 hi, %4, %3;\n\t"
            "mov.b32 %0, {lo, hi};\n\t"
            "}" : "=r"(u) : "f"(v.x), "f"(v.y), "f"(v.z), "f"(v.w));
        xw[k] = u;
    }
    #pragma unroll
    for (int o = 16; o; o >>= 1) s += __shfl_xor_sync(0xffffffffu, s, o);
    if (lane == 0) g_pooled[warp] = s * (1.0f / 576.0f);
}

// ============================================================
// 2) hidden[b,j] = silu(dot(pooled[b,:], fc1_w[j,:]) + fc1_b[j])
// ============================================================
__global__ void k_fc1(const float* __restrict__ fc1_w,
                      const float* __restrict__ fc1_b) {
    int warp = (blockIdx.x * blockDim.x + threadIdx.x) >> 5;
    int lane = threadIdx.x & 31;
    int b = warp >> 7;
    int j = warp & 127;
    const float4* pr = reinterpret_cast<const float4*>(g_pooled) + (size_t)b * (CC / 4);
    const float4* wr = reinterpret_cast<const float4*>(fc1_w)    + (size_t)j * (CC / 4);
    float s = 0.f;
    #pragma unroll 4
    for (int k = lane; k < CC / 4; k += 32) {
        float4 a = pr[k];
        float4 w = __ldg(&wr[k]);
        s += a.x * w.x + a.y * w.y + a.z * w.z + a.w * w.w;
    }
    #pragma unroll
    for (int o = 16; o; o >>= 1) s += __shfl_xor_sync(0xffffffffu, s, o);
    if (lane == 0) {
        float z = s + fc1_b[j];
        g_hidden[b * CHID + j] = z / (1.0f + expf(-z));
    }
}

// ============================================================
// 3) dw + fused beta partials.
// ============================================================
__global__ void k_fc2(const float* __restrict__ fc2_w,
                      const float* __restrict__ fc2_b,
                      const float* __restrict__ conv_b) {
    __shared__ float4 hs[8 * 32];
    __shared__ float  red[8][256];
    int rc = blockIdx.x & 31;
    int bg = blockIdx.x >> 5;
    int t  = threadIdx.x;

    hs[t] = reinterpret_cast<const float4*>(g_hidden)[bg * 256 + t];
    __syncthreads();

    int row = rc * 256 + t;
    int p   = rc >> 3;
    int chi = rc & 7;
    int c   = chi * 256 + t;
    const float4* wr = reinterpret_cast<const float4*>(fc2_w) + (size_t)row * 32;
    float acc[8];
    #pragma unroll
    for (int bb = 0; bb < 8; bb++) acc[bb] = 0.f;

    #pragma unroll 4
    for (int j4 = 0; j4 < 32; j4++) {
        float4 w = __ldg(&wr[j4]);
        #pragma unroll
        for (int bb = 0; bb < 8; bb++) {
            float4 h = hs[bb * 32 + j4];
            acc[bb] += w.x * h.x + w.y * h.y + w.z * h.z + w.w * h.w;
        }
    }
    float bias = fc2_b[row];
    float cb   = __ldg(&conv_b[c]);
    #pragma unroll
    for (int bb = 0; bb < 8; bb++) {
        float d = acc[bb] + bias;
        g_dw[(size_t)(bg * 8 + bb) * CP + row] = d;
        red[bb][t] = cb * d;
    }
    __syncthreads();

    int wid  = t >> 5;
    int lane = t & 31;
    float s = red[wid][lane] + red[wid][lane + 32] + red[wid][lane + 64] +
              red[wid][lane + 96] + red[wid][lane + 128] + red[wid][lane + 160] +
              red[wid][lane + 192] + red[wid][lane + 224];
    #pragma unroll
    for (int o = 16; o; o >>= 1) s += __shfl_xor_sync(0xffffffffu, s, o);
    if (lane == 0)
        g_beta_part[((size_t)chi * BB + bg * 8 + wid) * PP + p] = s;
}

// ============================================================
// 4) Fused einsum + softmax: warp-private cp.async pipelines,
//    HFMA2 inner loop (fp16x2 over hw-pairs), fp32 spill / 32 ch.
//    Block = (b, 64-hw chunk). 512 thr = 16 warps.
//    Warp w owns channels [w*128, (w+1)*128): 8 stages of 16 ch.
//    Lane: half = lane>>4 (channel of pair), qi = lane&15 (4-hw quad).
// ============================================================
__global__ void __launch_bounds__(512, 2) k_einsum(const float* __restrict__ conv_w,
                                                   float* __restrict__ out) {
    extern __shared__ char smem[];
    uint4* wcomb = reinterpret_cast<uint4*>(smem + SMEM_WCOMB);  // [CC]: 4 h2 per c
    unsigned int xs_base = smem_u32(smem);

    int blk = blockIdx.x;
    int b   = blk / NHWC;
    int hc  = blk % NHWC;
    int t   = threadIdx.x;
    int w   = t >> 5;
    int lane = t & 31;
    int half = lane >> 4;
    int qi   = lane & 15;

    unsigned int wring = xs_base + w * WRING_B;

    // copy geometry: warp-stage = 16 ch x 64 B = 64 x 16B chunks.
    int chA = lane >> 2, ckA = lane & 3;      // ch 0..7
    int chB = chA + 8;                        // ch 8..15
    unsigned int dA = wring + chA * 64 + ckA * 16;
    unsigned int dB = wring + chB * 64 + ckA * 16;
    const unsigned int* sA = g_xq + ((size_t)b * CC + w * 128 + chA) * HW4
                                  + hc * 16 + ckA * 4;
    const unsigned int* sB = g_xq + ((size_t)b * CC + w * 128 + chB) * HW4
                                  + hc * 16 + ckA * 4;

    // prologue: warp-stages 0,1,2 -> slots 0,1,2
    #pragma unroll
    for (int s = 0; s < 3; s++) {
        cp_async16(dA + s * 1024, sA + (size_t)(s * 16) * HW4);
        cp_async16(dB + s * 1024, sB + (size_t)(s * 16) * HW4);
        asm volatile("cp.async.commit_group;");
    }

    // wcomb fill: per (c,p) weight as duplicated h2
    const float* dwb = g_dw + (size_t)b * CP;
    for (int idx = t; idx < CC * PP; idx += 512) {
        int c = idx >> 2;
        int p = idx & 3;
        float wv = __ldg(&conv_w[c]) * dwb[p * CC + c];
        reinterpret_cast<__half2*>(wcomb)[idx] = __float2half2_rn(wv);
    }
    __syncthreads();

    float acc[4][4];
    #pragma unroll
    for (int h = 0; h < 4; h++)
        #pragma unroll
        for (int p = 0; p < 4; p++) acc[h][p] = 0.f;

    __half2 acc01[4], acc23[4];               // fp16 partials (hw01, hw23) x p
    #pragma unroll
    for (int p = 0; p < 4; p++) { acc01[p] = __half2half2(__ushort_as_half(0)); acc23[p] = acc01[p]; }

    #pragma unroll
    for (int s = 0; s < 8; s++) {
        if (s <= 5)      asm volatile("cp.async.wait_group 2;");
        else if (s == 6) asm volatile("cp.async.wait_group 1;");
        else             asm volatile("cp.async.wait_group 0;");
        __syncwarp();

        if (s <= 4) {
            int ss = s + 3;
            cp_async16(dA + (ss & 3) * 1024, sA + (size_t)(ss * 16) * HW4);
            cp_async16(dB + (ss & 3) * 1024, sB + (size_t)(ss * 16) * HW4);
            asm volatile("cp.async.commit_group;");
        }

        const char* stg = smem + w * WRING_B + (s & 3) * 1024;
        #pragma unroll
        for (int i = 0; i < 8; i++) {
            int chl = (i << 1) + half;                 // 0..15
            unsigned int v = *reinterpret_cast<const unsigned int*>(
                                 stg + chl * 64 + qi * 4);
            unsigned int h2lo, h2hi;
            asm("{\n\t"
                ".reg .b16 a, bz;\n\t"
                "mov.b32 {a, bz}, %2;\n\t"
                "cvt.rn.f16x2.e4m3x2 %0, a;\n\t"
                "cvt.rn.f16x2.e4m3x2 %1, bz;\n\t"
                "}" : "=r"(h2lo), "=r"(h2hi) : "r"(v));
            __half2 x01 = *reinterpret_cast<__half2*>(&h2lo);   // hw0, hw1
            __half2 x23 = *reinterpret_cast<__half2*>(&h2hi);   // hw2, hw3
            uint4 wv = wcomb[(w << 7) + (s << 4) + chl];
            __half2 w0 = *reinterpret_cast<__half2*>(&wv.x);
            __half2 w1 = *reinterpret_cast<__half2*>(&wv.y);
            __half2 w2 = *reinterpret_cast<__half2*>(&wv.z);
            __half2 w3 = *reinterpret_cast<__half2*>(&wv.w);
            acc01[0] = __hfma2(x01, w0, acc01[0]);
            acc01[1] = __hfma2(x01, w1, acc01[1]);
            acc01[2] = __hfma2(x01, w2, acc01[2]);
            acc01[3] = __hfma2(x01, w3, acc01[3]);
            acc23[0] = __hfma2(x23, w0, acc23[0]);
            acc23[1] = __hfma2(x23, w1, acc23[1]);
            acc23[2] = __hfma2(x23, w2, acc23[2]);
            acc23[3] = __hfma2(x23, w3, acc23[3]);
        }

        // spill fp16 partials to fp32 every 2 stages (32 channels)
        if (s & 1) {
            #pragma unroll
            for (int p = 0; p < 4; p++) {
                float2 f01 = __half22float2(acc01[p]);
                float2 f23 = __half22float2(acc23[p]);
                acc[0][p] += f01.x; acc[1][p] += f01.y;
                acc[2][p] += f23.x; acc[3][p] += f23.y;
                acc01[p] = __half2half2(__ushort_as_half(0));
                acc23[p] = acc01[p];
            }
        }
    }

    // fold channel halves: lane i += lane i+16 (same qi)
    #pragma unroll
    for (int h = 0; h < 4; h++)
        #pragma unroll
        for (int p = 0; p < 4; p++)
            acc[h][p] += __shfl_down_sync(0xffffffffu, acc[h][p], 16);

    // stash into this warp's (now dead) ring region
    if (half == 0) {
        float4* red = reinterpret_cast<float4*>(smem + w * WRING_B);
        #pragma unroll
        for (int h = 0; h < 4; h++)
            red[qi * 4 + h] = make_float4(acc[h][0], acc[h][1], acc[h][2], acc[h][3]);
    }
    __syncthreads();

    // 64 threads: sum 16 warps + beta, softmax over p, write out
    if (t < 64) {
        int rq = t >> 2;
        int rh = t & 3;
        float4 s = {0, 0, 0, 0};
        #pragma unroll
        for (int st = 0; st < 16; st++) {
            float4 v = reinterpret_cast<const float4*>(smem + st * WRING_B)[rq * 4 + rh];
            s.x += v.x; s.y += v.y; s.z += v.z; s.w += v.w;
        }
        #pragma unroll
        for (int chi = 0; chi < BCHUNK; chi++) {
            float4 bv = *reinterpret_cast<const float4*>(
                            &g_beta_part[((size_t)chi * BB + b) * PP]);
            s.x += bv.x; s.y += bv.y; s.z += bv.z; s.w += bv.w;
        }
        float m = fmaxf(fmaxf(s.x, s.y), fmaxf(s.z, s.w));
        float e0 = expf(s.x - m), e1 = expf(s.y - m), e2 = expf(s.z - m), e3 = expf(s.w - m);
        float inv = 1.f / (e0 + e1 + e2 + e3);
        size_t base = ((size_t)b * PP) * HWN + hc * 64 + t;
        out[base + 0 * HWN] = e0 * inv;
        out[base + 1 * HWN] = e1 * inv;
        out[base + 2 * HWN] = e2 * inv;
        out[base + 3 * HWN] = e3 * inv;
    }
}

extern "C" void kernel_launch(void* const* d_in, const int* in_sizes, int n_in,
                              void* d_out, int out_size) {
    const float* x      = (const float*)d_in[0];
    const float* fc1_w  = (const float*)d_in[1];
    const float* fc1_b  = (const float*)d_in[2];
    const float* fc2_w  = (const float*)d_in[3];
    const float* fc2_b  = (const float*)d_in[4];
    const float* conv_w = (const float*)d_in[5];
    const float* conv_b = (const float*)d_in[6];
    float* out = (float*)d_out;

    static int smem_set = 0;
    if (!smem_set) {
        cudaFuncSetAttribute(k_einsum, cudaFuncAttributeMaxDynamicSharedMemorySize,
                             SMEM_TOT);
        smem_set = 1;
    }

    k_pool  <<<(BB * CC) / 8, 256>>>(x);
    k_fc1   <<<(BB * CHID) / 8, 256>>>(fc1_w, fc1_b);
    k_fc2   <<<128, 256>>>(fc2_w, fc2_b, conv_b);
    k_einsum<<<BB * NHWC, 512, SMEM_TOT>>>(conv_w, out);
}